// round 5
// baseline (speedup 1.0000x reference)
#include <cuda_runtime.h>
#include <stdint.h>

// PHM embedding: out[tok, q*256 + j] = sum_k a[k,p,q] * s[k,i,j]
//   t = input[tok]; p = t / 12565; i = t % 12565
//   a: [4,4,4] (k,p,q) f32 ; s: [4,12565,256] f32 ; out: [16384,1024] f32
//
// cp.async 4-stage pipeline: in-flight gather bytes live in SMEM, not the
// register file. 256 thr = 4 tokens x 64 lanes; each thread prefetches and
// later consumes ITS OWN 4x16B -> no __syncthreads needed anywhere
// (cp.async.wait_group gives per-thread visibility).

static constexpr int N_ROWS = 12565;   // VOCAB_PAD / 4
static constexpr int EV4    = 64;      // 256 f32 cols / 4 per float4
static constexpr int TOKS   = 4;       // tokens per stage
static constexpr int STAGES = 4;
static constexpr int TPB    = 256;
static constexpr int GRID   = 444;     // 148 SMs x 3 blocks (smem-bound)

// dynamic smem: [STAGES][TOKS][4 rows][EV4] float4 = 64 KB

__device__ __forceinline__ void cp16(float4* dst_smem, const float4* src) {
    uint32_t d = (uint32_t)__cvta_generic_to_shared(dst_smem);
    asm volatile("cp.async.cg.shared.global [%0], [%1], 16;"
                 :: "r"(d), "l"(src) : "memory");
}
__device__ __forceinline__ void cp_commit() {
    asm volatile("cp.async.commit_group;" ::: "memory");
}
template <int N> __device__ __forceinline__ void cp_wait() {
    asm volatile("cp.async.wait_group %0;" :: "n"(N) : "memory");
}

__device__ __forceinline__ void stg_streaming(float4* p, float4 v) {
    asm volatile("st.global.cs.v4.f32 [%0], {%1,%2,%3,%4};"
                 :: "l"(p), "f"(v.x), "f"(v.y), "f"(v.z), "f"(v.w)
                 : "memory");
}

__global__ void __launch_bounds__(TPB, 3)
phm_embed_pipe(const int* __restrict__ inp,
               const float* __restrict__ a,
               const float4* __restrict__ s,
               float4* __restrict__ out,
               int n_grp)
{
    extern __shared__ float4 smem[];   // [STAGES][TOKS][4][EV4]

    const int lane = threadIdx.x & 63;
    const int tsub = threadIdx.x >> 6;

    // --- prologue: fill up to STAGES stages ---
#pragma unroll
    for (int k = 0; k < STAGES; k++) {
        const int gg = blockIdx.x + k * GRID;
        if (gg < n_grp) {
            const int tok = gg * TOKS + tsub;
            const int t = inp[tok];
            const int p = t / N_ROWS;
            const int i = t - p * N_ROWS;
            const float4* srow = s + (size_t)i * EV4 + lane;
            float4* dst = smem + ((k * TOKS + tsub) * 4) * EV4 + lane;
            cp16(dst + 0 * EV4, srow + 0 * N_ROWS * EV4);
            cp16(dst + 1 * EV4, srow + 1 * N_ROWS * EV4);
            cp16(dst + 2 * EV4, srow + 2 * N_ROWS * EV4);
            cp16(dst + 3 * EV4, srow + 3 * N_ROWS * EV4);
        }
        cp_commit();
    }

    // --- steady state ---
    int it = 0;
    for (int g = blockIdx.x; g < n_grp; g += GRID, it++) {
        cp_wait<STAGES - 1>();                 // oldest group complete
        const int stc = it & (STAGES - 1);

        const int tok = g * TOKS + tsub;
        const int t = inp[tok];                // L1-hot (read at prefetch)
        const int p = t / N_ROWS;

        const float4* buf = smem + ((stc * TOKS + tsub) * 4) * EV4 + lane;
        const float4 sv0 = buf[0 * EV4];
        const float4 sv1 = buf[1 * EV4];
        const float4 sv2 = buf[2 * EV4];
        const float4 sv3 = buf[3 * EV4];

        const float* ap = a + p * 4;           // a[k,p,q] = a[k*16+p*4+q]
        float4* outp = out + (size_t)tok * 256 + lane;

#pragma unroll
        for (int q = 0; q < 4; q++) {
            const float c0 = __ldg(&ap[ 0 + q]);
            const float c1 = __ldg(&ap[16 + q]);
            const float c2 = __ldg(&ap[32 + q]);
            const float c3 = __ldg(&ap[48 + q]);
            float4 o;
            o.x = c0 * sv0.x + c1 * sv1.x + c2 * sv2.x + c3 * sv3.x;
            o.y = c0 * sv0.y + c1 * sv1.y + c2 * sv2.y + c3 * sv3.y;
            o.z = c0 * sv0.z + c1 * sv1.z + c2 * sv2.z + c3 * sv3.z;
            o.w = c0 * sv0.w + c1 * sv1.w + c2 * sv2.w + c3 * sv3.w;
            stg_streaming(outp + q * EV4, o);
        }

        // --- prefetch group g + STAGES*GRID into the stage just freed ---
        const int gn = g + STAGES * GRID;
        if (gn < n_grp) {
            const int tokn = gn * TOKS + tsub;
            const int tn = inp[tokn];
            const int pn = tn / N_ROWS;
            const int in_ = tn - pn * N_ROWS;
            const float4* srow = s + (size_t)in_ * EV4 + lane;
            float4* dst = smem + ((stc * TOKS + tsub) * 4) * EV4 + lane;
            cp16(dst + 0 * EV4, srow + 0 * N_ROWS * EV4);
            cp16(dst + 1 * EV4, srow + 1 * N_ROWS * EV4);
            cp16(dst + 2 * EV4, srow + 2 * N_ROWS * EV4);
            cp16(dst + 3 * EV4, srow + 3 * N_ROWS * EV4);
        }
        cp_commit();                           // keep group accounting aligned
    }
}

extern "C" void kernel_launch(void* const* d_in, const int* in_sizes, int n_in,
                              void* d_out, int out_size)
{
    const int*    inp = (const int*)d_in[0];    // [8,2048] int32
    const float*  a   = (const float*)d_in[1];  // [4,4,4]
    const float4* s   = (const float4*)d_in[2]; // [4,12565,256] f32 as float4
    float4*       out = (float4*)d_out;

    const int n_tok = in_sizes[0];              // 16384
    const int n_grp = n_tok / TOKS;             // 4096

    const int smem_bytes = STAGES * TOKS * 4 * EV4 * sizeof(float4); // 65536
    static_assert(STAGES * TOKS * 4 * EV4 * sizeof(float4) == 65536, "");
    cudaFuncSetAttribute(phm_embed_pipe,
                         cudaFuncAttributeMaxDynamicSharedMemorySize, smem_bytes);

    phm_embed_pipe<<<GRID, TPB, smem_bytes>>>(inp, a, s, out, n_grp);
}